// round 1
// baseline (speedup 1.0000x reference)
#include <cuda_runtime.h>
#include <cuda_bf16.h>
#include <math.h>

#define D      256
#define NMAX   8192
#define TM     128
#define TN     128
#define KC     16
#define LDA    (TM + 4)
#define EPSF   1e-8f

__device__ float               g_xn[NMAX * D];        // normalized x
__device__ unsigned long long  g_best[NMAX];          // packed (sortable dot, ~idx)
__device__ float               g_nl[NMAX];            // -log(dist+eps) per row

// Order-preserving float -> uint, packed with complemented index so that
// larger key == (larger dot, then smaller index)  [matches jnp.argmax tie-break]
__device__ __forceinline__ unsigned long long pack_key(float v, unsigned idx) {
    unsigned u = __float_as_uint(v);
    u = (u & 0x80000000u) ? ~u : (u | 0x80000000u);
    return ((unsigned long long)u << 32) | (0xFFFFFFFFu - idx);
}

// ---------------------------------------------------------------------------
// Kernel 1: row L2-normalize + reset argmax state
// ---------------------------------------------------------------------------
__global__ void k_normalize(const float* __restrict__ x, int n) {
    int row = blockIdx.x;
    int t   = threadIdx.x;                    // 256 threads, 1 elem each
    float v = x[row * D + t];
    float s = v * v;
    #pragma unroll
    for (int o = 16; o; o >>= 1) s += __shfl_down_sync(0xffffffffu, s, o);
    __shared__ float ws[8];
    if ((t & 31) == 0) ws[t >> 5] = s;
    __syncthreads();
    if (t < 8) {
        float z = ws[t];
        #pragma unroll
        for (int o = 4; o; o >>= 1) z += __shfl_down_sync(0x000000ffu, z, o);
        if (t == 0) ws[0] = z;
    }
    __syncthreads();
    float norm = fmaxf(sqrtf(ws[0]), EPSF);
    g_xn[row * D + t] = v / norm;
    if (t == 0) g_best[row] = 0ull;
}

// ---------------------------------------------------------------------------
// Kernel 2: fused x@xT + per-row argmax (upper-triangular tiles, symmetric
// updates).  128x128 tile, KC=16, 8x8 microtile, double-buffered smem.
// ---------------------------------------------------------------------------
__global__ __launch_bounds__(256, 2) void k_dots(int n) {
    const int bi = blockIdx.y, bj = blockIdx.x;
    if (bj < bi) return;

    __shared__ float As[2][KC][LDA];
    __shared__ float Bs[2][KC][LDA];
    __shared__ unsigned long long colred[TN][9];   // 8 warp-group partials + pad

    const int tid = threadIdx.x;
    const int tx  = tid & 15;          // 0..15 -> col group
    const int ty  = tid >> 4;          // 0..15 -> row group
    const int rowBase = bi * TM;
    const int colBase = bj * TN;

    float acc[8][8];
    #pragma unroll
    for (int i = 0; i < 8; i++)
        #pragma unroll
        for (int j = 0; j < 8; j++) acc[i][j] = 0.f;

    // prefetch registers: 2 tasks/thread, each a float4 for A and B tiles
    float4 pa[2], pb[2];
    const int r0 = (tid        ) >> 2, q0 = (tid        ) & 3;
    const int r1 = (tid + 256  ) >> 2, q1 = (tid + 256  ) & 3;

    auto ldg_tile = [&](int k0) {
        pa[0] = *(const float4*)&g_xn[(rowBase + r0) * D + k0 + q0 * 4];
        pb[0] = *(const float4*)&g_xn[(colBase + r0) * D + k0 + q0 * 4];
        pa[1] = *(const float4*)&g_xn[(rowBase + r1) * D + k0 + q1 * 4];
        pb[1] = *(const float4*)&g_xn[(colBase + r1) * D + k0 + q1 * 4];
    };
    auto sts_tile = [&](int buf) {
        As[buf][q0*4+0][r0] = pa[0].x; As[buf][q0*4+1][r0] = pa[0].y;
        As[buf][q0*4+2][r0] = pa[0].z; As[buf][q0*4+3][r0] = pa[0].w;
        Bs[buf][q0*4+0][r0] = pb[0].x; Bs[buf][q0*4+1][r0] = pb[0].y;
        Bs[buf][q0*4+2][r0] = pb[0].z; Bs[buf][q0*4+3][r0] = pb[0].w;
        As[buf][q1*4+0][r1] = pa[1].x; As[buf][q1*4+1][r1] = pa[1].y;
        As[buf][q1*4+2][r1] = pa[1].z; As[buf][q1*4+3][r1] = pa[1].w;
        Bs[buf][q1*4+0][r1] = pb[1].x; Bs[buf][q1*4+1][r1] = pb[1].y;
        Bs[buf][q1*4+2][r1] = pb[1].z; Bs[buf][q1*4+3][r1] = pb[1].w;
    };

    ldg_tile(0);
    sts_tile(0);
    __syncthreads();

    const int nk = D / KC;  // 16
    for (int kt = 0; kt < nk; kt++) {
        const int buf = kt & 1;
        if (kt + 1 < nk) ldg_tile((kt + 1) * KC);

        #pragma unroll
        for (int k = 0; k < KC; k++) {
            float a[8], b[8];
            *(float4*)&a[0] = *(const float4*)&As[buf][k][ty * 8];
            *(float4*)&a[4] = *(const float4*)&As[buf][k][ty * 8 + 4];
            *(float4*)&b[0] = *(const float4*)&Bs[buf][k][tx * 8];
            *(float4*)&b[4] = *(const float4*)&Bs[buf][k][tx * 8 + 4];
            #pragma unroll
            for (int i = 0; i < 8; i++)
                #pragma unroll
                for (int j = 0; j < 8; j++)
                    acc[i][j] = fmaf(a[i], b[j], acc[i][j]);
        }
        if (kt + 1 < nk) sts_tile(buf ^ 1);
        __syncthreads();
    }

    // ---- epilogue: row-wise argmax (rows of this tile over its 128 cols) ----
    #pragma unroll
    for (int i = 0; i < 8; i++) {
        const int gr = rowBase + ty * 8 + i;
        unsigned long long best = 0ull;
        #pragma unroll
        for (int j = 0; j < 8; j++) {
            const int gc = colBase + tx * 8 + j;
            if (gc != gr) {                       // diagonal excluded (set to -1 in ref)
                unsigned long long key = pack_key(acc[i][j], (unsigned)gc);
                best = (key > best) ? key : best;
            }
        }
        // reduce over the 16 lanes sharing this row (same ty, tx 0..15 contiguous)
        #pragma unroll
        for (int off = 8; off; off >>= 1) {
            unsigned long long o = __shfl_down_sync(0xffffffffu, best, off, 16);
            best = (o > best) ? o : best;
        }
        if (tx == 0) atomicMax(&g_best[gr], best);
    }

    // ---- symmetric part: col-wise argmax (only strictly-upper blocks) ----
    if (bi != bj) {
        unsigned long long cb[8];
        #pragma unroll
        for (int j = 0; j < 8; j++) {
            unsigned long long best = 0ull;
            #pragma unroll
            for (int i = 0; i < 8; i++) {
                unsigned long long key =
                    pack_key(acc[i][j], (unsigned)(rowBase + ty * 8 + i));
                best = (key > best) ? key : best;
            }
            // fold the two ty's that share a warp (lane ^ 16)
            unsigned long long o = __shfl_xor_sync(0xffffffffu, best, 16);
            cb[j] = (o > best) ? o : best;
        }
        if ((ty & 1) == 0) {
            #pragma unroll
            for (int j = 0; j < 8; j++)
                colred[tx * 8 + j][ty >> 1] = cb[j];
        }
        __syncthreads();
        if (tid < TN) {
            unsigned long long b = colred[tid][0];
            #pragma unroll
            for (int w = 1; w < 8; w++) {
                unsigned long long o = colred[tid][w];
                b = (o > b) ? o : b;
            }
            atomicMax(&g_best[colBase + tid], b);
        }
    }
}

// ---------------------------------------------------------------------------
// Kernel 3: per-row distance to nearest neighbor, -log(dist + eps)
// ---------------------------------------------------------------------------
__global__ void k_dist(int n) {
    int row = blockIdx.x;
    int t   = threadIdx.x;   // 256
    unsigned idx = 0xFFFFFFFFu - (unsigned)(g_best[row] & 0xFFFFFFFFull);
    float d = g_xn[row * D + t] - g_xn[idx * D + t] + EPSF;
    float s = d * d;
    #pragma unroll
    for (int o = 16; o; o >>= 1) s += __shfl_down_sync(0xffffffffu, s, o);
    __shared__ float ws[8];
    if ((t & 31) == 0) ws[t >> 5] = s;
    __syncthreads();
    if (t < 8) {
        float z = ws[t];
        #pragma unroll
        for (int o = 4; o; o >>= 1) z += __shfl_down_sync(0x000000ffu, z, o);
        if (t == 0) g_nl[row] = -logf(sqrtf(z) + EPSF);
    }
}

// ---------------------------------------------------------------------------
// Kernel 4: deterministic fixed-order mean reduction
// ---------------------------------------------------------------------------
__global__ void k_reduce(float* __restrict__ out, int n) {
    __shared__ float sm[256];
    int t = threadIdx.x;
    float s = 0.f;
    for (int i = t; i < n; i += 256) s += g_nl[i];
    sm[t] = s;
    __syncthreads();
    #pragma unroll
    for (int o = 128; o; o >>= 1) {
        if (t < o) sm[t] += sm[t + o];
        __syncthreads();
    }
    if (t == 0) out[0] = sm[0] / (float)n;
}

extern "C" void kernel_launch(void* const* d_in, const int* in_sizes, int n_in,
                              void* d_out, int out_size) {
    const float* student = (const float*)d_in[0];
    int n = in_sizes[0] / D / 10;          // B = 81920/10 = 8192
    if (n > NMAX) n = NMAX;

    k_normalize<<<n, 256>>>(student, n);
    dim3 grid(n / TM, n / TM);             // upper triangle handled in-kernel
    k_dots<<<grid, 256>>>(n);
    k_dist<<<n, 256>>>(n);
    k_reduce<<<1, 256>>>((float*)d_out, n);
}

// round 3
// speedup vs baseline: 4.2262x; 4.2262x over previous
#include <cuda_runtime.h>
#include <cuda_bf16.h>
#include <math.h>
#include <stdint.h>

#define D      256
#define NMAX   8192
#define TB     128
#define EPSF   1e-8f

#define KC     64                      // k-chunk (bf16 elems)
#define ROWB   144                     // bytes per smem row: 64*2 + 16 pad
#define TILEB  (128 * ROWB)            // 18432 B per tile chunk
#define BUFB   (2 * TILEB)             // A + B
#define SMEMB  (2 * BUFB)              // double buffered = 73728 B

__device__ __nv_bfloat16       g_xb[NMAX * D];   // normalized x, bf16
__device__ float               g_xn[NMAX * D];   // normalized x, fp32
__device__ unsigned long long  g_best[NMAX];     // packed (sortable dot, ~idx)
__device__ float               g_nl[NMAX];       // -log(dist+eps)

__device__ __forceinline__ uint32_t smem_u32(const void* p) {
    uint32_t a;
    asm("{ .reg .u64 t; cvta.to.shared.u64 t, %1; cvt.u32.u64 %0, t; }" : "=r"(a) : "l"(p));
    return a;
}

#define LDSM_X4(r, a) \
    asm volatile("ldmatrix.sync.aligned.m8n8.x4.shared.b16 {%0,%1,%2,%3}, [%4];" \
        : "=r"((r)[0]), "=r"((r)[1]), "=r"((r)[2]), "=r"((r)[3]) : "r"(a))

#define MMA16816(c, a, b0, b1) \
    asm volatile("mma.sync.aligned.m16n8k16.row.col.f32.bf16.bf16.f32 " \
        "{%0,%1,%2,%3}, {%4,%5,%6,%7}, {%8,%9}, {%0,%1,%2,%3};" \
        : "+f"((c)[0]), "+f"((c)[1]), "+f"((c)[2]), "+f"((c)[3]) \
        : "r"((a)[0]), "r"((a)[1]), "r"((a)[2]), "r"((a)[3]), "r"(b0), "r"(b1))

#define CP_ASYNC16(sa, g) \
    asm volatile("cp.async.cg.shared.global [%0], [%1], 16;" :: "r"(sa), "l"(g))

__device__ __forceinline__ unsigned long long u64max(unsigned long long a,
                                                     unsigned long long b) {
    return a > b ? a : b;
}

// ---------------------------------------------------------------- kernel 1
__global__ void k_normalize(const float* __restrict__ x, int n) {
    int row = blockIdx.x, t = threadIdx.x;        // 256 threads, 1 elem each
    float v = x[row * D + t];
    float s = v * v;
    #pragma unroll
    for (int o = 16; o; o >>= 1) s += __shfl_down_sync(0xffffffffu, s, o);
    __shared__ float ws[8];
    if ((t & 31) == 0) ws[t >> 5] = s;
    __syncthreads();
    if (t < 8) {
        float z = ws[t];
        #pragma unroll
        for (int o = 4; o; o >>= 1) z += __shfl_down_sync(0x000000ffu, z, o);
        if (t == 0) ws[0] = z;
    }
    __syncthreads();
    float xn = v / fmaxf(sqrtf(ws[0]), EPSF);
    g_xn[row * D + t] = xn;
    g_xb[row * D + t] = __float2bfloat16(xn);
    if (t == 0) g_best[row] = 0ull;
}

// ---------------------------------------------------------------- kernel 2
// One CTA per upper-triangular 128x128 tile. cp.async double-buffered smem,
// mma.sync bf16 HMMA, register-fragment argmax epilogue (rows + sym cols).
__global__ __launch_bounds__(256, 2) void k_dots_mma(int nb) {
    extern __shared__ char smem[];
    const uint32_t sb = smem_u32(smem);
    const int tid = threadIdx.x, lane = tid & 31, wid = tid >> 5;
    const int warp_m = wid >> 2, warp_n = wid & 3;

    // decode triangular tile index -> (bi, bj)
    int t = blockIdx.x, bi = 0;
    while (t >= nb - bi) { t -= nb - bi; bi++; }
    const int bj = bi + t;
    const bool diag = (bi == bj);
    const int rowBase = bi * TB, colBase = bj * TB;

    float acc[4][4][4];
    #pragma unroll
    for (int i = 0; i < 4; i++)
        #pragma unroll
        for (int j = 0; j < 4; j++)
            #pragma unroll
            for (int k = 0; k < 4; k++) acc[i][j][k] = 0.f;

    auto load_chunk = [&](int c, int s) {
        const char* gA = (const char*)g_xb + ((size_t)rowBase * D + c * KC) * 2;
        const char* gB = (const char*)g_xb + ((size_t)colBase * D + c * KC) * 2;
        const uint32_t base = sb + s * BUFB;
        #pragma unroll
        for (int i = 0; i < 4; i++) {
            int tr = tid + 256 * i;          // 0..1023 transfers of 16B
            int r = tr >> 3, seg = tr & 7;
            uint32_t so = r * ROWB + seg * 16;
            CP_ASYNC16(base + so,          gA + (size_t)r * (D * 2) + seg * 16);
            CP_ASYNC16(base + TILEB + so,  gB + (size_t)r * (D * 2) + seg * 16);
        }
        asm volatile("cp.async.commit_group;" ::: "memory");
    };

    load_chunk(0, 0);
    load_chunk(1, 1);

    #pragma unroll 1
    for (int c = 0; c < 4; c++) {
        const int s = c & 1;
        if (c < 3) asm volatile("cp.async.wait_group 1;" ::: "memory");
        else       asm volatile("cp.async.wait_group 0;" ::: "memory");
        __syncthreads();

        const uint32_t Abase = sb + s * BUFB;
        const uint32_t Bbase = Abase + TILEB;
        // ldmatrix lane address patterns (canonical m16k16 / k16n16)
        const uint32_t aAddr = Abase + (warp_m * 64 + (lane & 15)) * ROWB
                                     + (lane >> 4) * 16;
        const uint32_t bAddr = Bbase + (warp_n * 32 + (lane & 7) + ((lane >> 4) << 3)) * ROWB
                                     + ((lane >> 3) & 1) * 16;

        #pragma unroll
        for (int ks = 0; ks < 4; ks++) {
            uint32_t a_[4][4], b_[2][4];
            #pragma unroll
            for (int mi = 0; mi < 4; mi++)
                LDSM_X4(a_[mi], aAddr + mi * 16 * ROWB + ks * 32);
            #pragma unroll
            for (int p = 0; p < 2; p++)
                LDSM_X4(b_[p], bAddr + p * 16 * ROWB + ks * 32);
            #pragma unroll
            for (int mi = 0; mi < 4; mi++)
                #pragma unroll
                for (int ni = 0; ni < 4; ni++) {
                    const uint32_t* bp = b_[ni >> 1];
                    if (ni & 1) MMA16816(acc[mi][ni], a_[mi], bp[2], bp[3]);
                    else        MMA16816(acc[mi][ni], a_[mi], bp[0], bp[1]);
                }
        }
        __syncthreads();
        if (c + 2 < 4) load_chunk(c + 2, s);
    }

    // ---- epilogue: row argmax ----
    #pragma unroll
    for (int mi = 0; mi < 4; mi++)
        #pragma unroll
        for (int h = 0; h < 2; h++) {
            const int r = rowBase + warp_m * 64 + mi * 16 + (lane >> 2) + h * 8;
            unsigned long long best = 0ull;
            #pragma unroll
            for (int ni = 0; ni < 4; ni++)
                #pragma unroll
                for (int j = 0; j < 2; j++) {
                    const int col = colBase + warp_n * 32 + ni * 8 + 2 * (lane & 3) + j;
                    unsigned u = __float_as_uint(acc[mi][ni][h * 2 + j]);
                    u = ((int)u < 0) ? ~u : (u | 0x80000000u);
                    unsigned long long key = ((unsigned long long)u << 32)
                                           | (0xFFFFFFFFu - (unsigned)col);
                    if (col != r) best = u64max(best, key);
                }
            best = u64max(best, __shfl_xor_sync(0xffffffffu, best, 1));
            best = u64max(best, __shfl_xor_sync(0xffffffffu, best, 2));
            if ((lane & 3) == 0) atomicMax(&g_best[r], best);
        }

    // ---- symmetric col argmax (off-diagonal tiles only) ----
    if (!diag) {
        #pragma unroll
        for (int ni = 0; ni < 4; ni++)
            #pragma unroll
            for (int j = 0; j < 2; j++) {
                const int col = colBase + warp_n * 32 + ni * 8 + 2 * (lane & 3) + j;
                unsigned long long best = 0ull;
                #pragma unroll
                for (int mi = 0; mi < 4; mi++)
                    #pragma unroll
                    for (int h = 0; h < 2; h++) {
                        const int r = rowBase + warp_m * 64 + mi * 16 + (lane >> 2) + h * 8;
                        unsigned u = __float_as_uint(acc[mi][ni][h * 2 + j]);
                        u = ((int)u < 0) ? ~u : (u | 0x80000000u);
                        unsigned long long key = ((unsigned long long)u << 32)
                                               | (0xFFFFFFFFu - (unsigned)r);
                        best = u64max(best, key);
                    }
                best = u64max(best, __shfl_xor_sync(0xffffffffu, best, 4));
                best = u64max(best, __shfl_xor_sync(0xffffffffu, best, 8));
                best = u64max(best, __shfl_xor_sync(0xffffffffu, best, 16));
                if (lane < 4) atomicMax(&g_best[col], best);
            }
    }
}

// ---------------------------------------------------------------- kernel 3
__global__ void k_dist(int n) {
    int row = blockIdx.x, t = threadIdx.x;
    unsigned idx = 0xFFFFFFFFu - (unsigned)(g_best[row] & 0xFFFFFFFFull);
    float d = g_xn[row * D + t] - g_xn[idx * D + t] + EPSF;
    float s = d * d;
    #pragma unroll
    for (int o = 16; o; o >>= 1) s += __shfl_down_sync(0xffffffffu, s, o);
    __shared__ float ws[8];
    if ((t & 31) == 0) ws[t >> 5] = s;
    __syncthreads();
    if (t < 8) {
        float z = ws[t];
        #pragma unroll
        for (int o = 4; o; o >>= 1) z += __shfl_down_sync(0x000000ffu, z, o);
        if (t == 0) g_nl[row] = -logf(sqrtf(z) + EPSF);
    }
}

// ---------------------------------------------------------------- kernel 4
__global__ void k_reduce(float* __restrict__ out, int n) {
    __shared__ float sm[1024];
    int t = threadIdx.x;
    float s = 0.f;
    for (int i = t; i < n; i += 1024) s += g_nl[i];
    sm[t] = s;
    __syncthreads();
    #pragma unroll
    for (int o = 512; o; o >>= 1) {
        if (t < o) sm[t] += sm[t + o];
        __syncthreads();
    }
    if (t == 0) out[0] = sm[0] / (float)n;
}

// ---------------------------------------------------------------- launch
extern "C" void kernel_launch(void* const* d_in, const int* in_sizes, int n_in,
                              void* d_out, int out_size) {
    const float* student = (const float*)d_in[0];
    int n = in_sizes[0] / D / 10;          // B = 81920/10 = 8192
    if (n > NMAX) n = NMAX;
    const int nb = n / TB;
    const int ntiles = nb * (nb + 1) / 2;

    static bool attr_set = false;
    if (!attr_set) {
        cudaFuncSetAttribute(k_dots_mma,
                             cudaFuncAttributeMaxDynamicSharedMemorySize, SMEMB);
        attr_set = true;
    }

    k_normalize<<<n, 256>>>(student, n);
    k_dots_mma<<<ntiles, 256, SMEMB>>>(nb);
    k_dist<<<n, 256>>>(n);
    k_reduce<<<1, 1024>>>((float*)d_out, n);
}

// round 4
// speedup vs baseline: 4.2570x; 1.0073x over previous
#include <cuda_runtime.h>
#include <cuda_bf16.h>
#include <math.h>
#include <stdint.h>

#define D      256
#define NMAX   8192
#define TB     128
#define EPSF   1e-8f

#define KC     64                      // k-chunk (bf16 elems)
#define ROWB   144                     // bytes per smem row: 64*2 + 16 pad
#define TILEB  (128 * ROWB)            // 18432 B per tile chunk
#define BUFB   (2 * TILEB)             // A + B
#define SMEMB  (2 * BUFB)              // double buffered = 73728 B

__device__ __nv_bfloat16       g_xb[NMAX * D];
__device__ float               g_xn[NMAX * D];
__device__ unsigned long long  g_best[NMAX];
__device__ float               g_part[256];
__device__ int                 g_ctr;

__device__ __forceinline__ uint32_t smem_u32(const void* p) {
    uint32_t a;
    asm("{ .reg .u64 t; cvta.to.shared.u64 t, %1; cvt.u32.u64 %0, t; }" : "=r"(a) : "l"(p));
    return a;
}
#define LDSM_X4(r, a) \
    asm volatile("ldmatrix.sync.aligned.m8n8.x4.shared.b16 {%0,%1,%2,%3}, [%4];" \
        : "=r"((r)[0]), "=r"((r)[1]), "=r"((r)[2]), "=r"((r)[3]) : "r"(a))
#define MMA16816(c, a, b0, b1) \
    asm volatile("mma.sync.aligned.m16n8k16.row.col.f32.bf16.bf16.f32 " \
        "{%0,%1,%2,%3}, {%4,%5,%6,%7}, {%8,%9}, {%0,%1,%2,%3};" \
        : "+f"((c)[0]), "+f"((c)[1]), "+f"((c)[2]), "+f"((c)[3]) \
        : "r"((a)[0]), "r"((a)[1]), "r"((a)[2]), "r"((a)[3]), "r"(b0), "r"(b1))
#define CP_ASYNC16(sa, g) \
    asm volatile("cp.async.cg.shared.global [%0], [%1], 16;" :: "r"(sa), "l"(g))

__device__ __forceinline__ unsigned long long u64max(unsigned long long a,
                                                     unsigned long long b) {
    return a > b ? a : b;
}

// ---------------------------------------------------------------- kernel 1
// warp-per-row normalize: float4 loads, shfl-only reduction.
__global__ void k_normalize(const float* __restrict__ x, int n) {
    const int lane = threadIdx.x & 31, w = threadIdx.x >> 5;
    const int row = blockIdx.x * 8 + w;
    if (row >= n) return;
    const float4* xr = (const float4*)(x + (size_t)row * D) + lane * 2;
    float4 v0 = xr[0], v1 = xr[1];
    float s = v0.x*v0.x + v0.y*v0.y + v0.z*v0.z + v0.w*v0.w
            + v1.x*v1.x + v1.y*v1.y + v1.z*v1.z + v1.w*v1.w;
    #pragma unroll
    for (int o = 16; o; o >>= 1) s += __shfl_xor_sync(0xffffffffu, s, o);
    const float inv = 1.f / fmaxf(sqrtf(s), EPSF);
    v0.x*=inv; v0.y*=inv; v0.z*=inv; v0.w*=inv;
    v1.x*=inv; v1.y*=inv; v1.z*=inv; v1.w*=inv;
    float4* on = (float4*)(g_xn + (size_t)row * D) + lane * 2;
    on[0] = v0; on[1] = v1;
    __nv_bfloat162 b[4];
    b[0] = __floats2bfloat162_rn(v0.x, v0.y);
    b[1] = __floats2bfloat162_rn(v0.z, v0.w);
    b[2] = __floats2bfloat162_rn(v1.x, v1.y);
    b[3] = __floats2bfloat162_rn(v1.z, v1.w);
    *((uint4*)(g_xb + (size_t)row * D) + lane) = *(uint4*)b;
    if (lane == 0) g_best[row] = 0ull;
    if (blockIdx.x == 0 && threadIdx.x == 0) g_ctr = 0;
}

// ---------------------------------------------------------------- kernel 2
// One CTA (128 thr, 4 warps, 2x2 grid of 64x64 warp tiles) per upper-tri
// 128x128 tile. cp.async double buffer, bf16 HMMA, register argmax epilogue.
__global__ __launch_bounds__(128) void k_dots_mma(int nb) {
    extern __shared__ char smem[];
    const uint32_t sb = smem_u32(smem);
    const int tid = threadIdx.x, lane = tid & 31, wid = tid >> 5;
    const int warp_m = wid >> 1, warp_n = wid & 1;

    int t = blockIdx.x, bi = 0;
    while (t >= nb - bi) { t -= nb - bi; bi++; }
    const int bj = bi + t;
    const bool diag = (bi == bj);
    const int rowBase = bi * TB, colBase = bj * TB;

    float acc[4][8][4];
    #pragma unroll
    for (int i = 0; i < 4; i++)
        #pragma unroll
        for (int j = 0; j < 8; j++)
            #pragma unroll
            for (int k = 0; k < 4; k++) acc[i][j][k] = 0.f;

    auto load_chunk = [&](int c, int s) {
        const char* gA = (const char*)g_xb + ((size_t)rowBase * D + c * KC) * 2;
        const char* gB = (const char*)g_xb + ((size_t)colBase * D + c * KC) * 2;
        const uint32_t base = sb + s * BUFB;
        #pragma unroll
        for (int i = 0; i < 8; i++) {
            int tr = tid + 128 * i;          // 0..1023 transfers of 16B
            int r = tr >> 3, seg = tr & 7;
            uint32_t so = r * ROWB + seg * 16;
            CP_ASYNC16(base + so,         gA + (size_t)r * (D * 2) + seg * 16);
            CP_ASYNC16(base + TILEB + so, gB + (size_t)r * (D * 2) + seg * 16);
        }
        asm volatile("cp.async.commit_group;" ::: "memory");
    };

    load_chunk(0, 0);
    load_chunk(1, 1);

    #pragma unroll 1
    for (int c = 0; c < 4; c++) {
        const int s = c & 1;
        if (c < 3) asm volatile("cp.async.wait_group 1;" ::: "memory");
        else       asm volatile("cp.async.wait_group 0;" ::: "memory");
        __syncthreads();

        const uint32_t Abase = sb + s * BUFB;
        const uint32_t Bbase = Abase + TILEB;
        const uint32_t aAddr = Abase + (warp_m * 64 + (lane & 15)) * ROWB
                                     + (lane >> 4) * 16;
        const uint32_t bAddr = Bbase + (warp_n * 64 + (lane & 7) + ((lane >> 4) << 3)) * ROWB
                                     + ((lane >> 3) & 1) * 16;

        #pragma unroll
        for (int ks = 0; ks < 4; ks++) {
            uint32_t a_[4][4], b_[4][4];
            #pragma unroll
            for (int mi = 0; mi < 4; mi++)
                LDSM_X4(a_[mi], aAddr + mi * 16 * ROWB + ks * 32);
            #pragma unroll
            for (int p = 0; p < 4; p++)
                LDSM_X4(b_[p], bAddr + p * 16 * ROWB + ks * 32);
            #pragma unroll
            for (int mi = 0; mi < 4; mi++)
                #pragma unroll
                for (int ni = 0; ni < 8; ni++) {
                    const uint32_t* bp = b_[ni >> 1];
                    if (ni & 1) MMA16816(acc[mi][ni], a_[mi], bp[2], bp[3]);
                    else        MMA16816(acc[mi][ni], a_[mi], bp[0], bp[1]);
                }
        }
        __syncthreads();
        if (c + 2 < 4) load_chunk(c + 2, s);
    }

    // ---- row argmax ----
    #pragma unroll
    for (int mi = 0; mi < 4; mi++)
        #pragma unroll
        for (int h = 0; h < 2; h++) {
            const int r = rowBase + warp_m * 64 + mi * 16 + (lane >> 2) + h * 8;
            unsigned long long best = 0ull;
            #pragma unroll
            for (int ni = 0; ni < 8; ni++)
                #pragma unroll
                for (int j = 0; j < 2; j++) {
                    const int col = colBase + warp_n * 64 + ni * 8 + 2 * (lane & 3) + j;
                    unsigned u = __float_as_uint(acc[mi][ni][h * 2 + j]);
                    u = ((int)u < 0) ? ~u : (u | 0x80000000u);
                    unsigned long long key = ((unsigned long long)u << 32)
                                           | (0xFFFFFFFFu - (unsigned)col);
                    if (col != r) best = u64max(best, key);
                }
            best = u64max(best, __shfl_xor_sync(0xffffffffu, best, 1));
            best = u64max(best, __shfl_xor_sync(0xffffffffu, best, 2));
            if ((lane & 3) == 0) atomicMax(&g_best[r], best);
        }

    // ---- symmetric col argmax (off-diagonal tiles) ----
    if (!diag) {
        #pragma unroll
        for (int ni = 0; ni < 8; ni++)
            #pragma unroll
            for (int j = 0; j < 2; j++) {
                const int col = colBase + warp_n * 64 + ni * 8 + 2 * (lane & 3) + j;
                unsigned long long best = 0ull;
                #pragma unroll
                for (int mi = 0; mi < 4; mi++)
                    #pragma unroll
                    for (int h = 0; h < 2; h++) {
                        const int r = rowBase + warp_m * 64 + mi * 16 + (lane >> 2) + h * 8;
                        unsigned u = __float_as_uint(acc[mi][ni][h * 2 + j]);
                        u = ((int)u < 0) ? ~u : (u | 0x80000000u);
                        unsigned long long key = ((unsigned long long)u << 32)
                                               | (0xFFFFFFFFu - (unsigned)r);
                        best = u64max(best, key);
                    }
                best = u64max(best, __shfl_xor_sync(0xffffffffu, best, 4));
                best = u64max(best, __shfl_xor_sync(0xffffffffu, best, 8));
                best = u64max(best, __shfl_xor_sync(0xffffffffu, best, 16));
                if (lane < 4) atomicMax(&g_best[col], best);
            }
    }
}

// ---------------------------------------------------------------- kernel 3
// fused distance + deterministic mean reduction (last block finishes).
#define RB 128                          // blocks
__global__ void k_dist_reduce(float* __restrict__ out, int n) {
    const int lane = threadIdx.x & 31, w = threadIdx.x >> 5;
    const int rows_per_warp = n / (RB * 8);           // 8 warps/block
    float wsum = 0.f;
    for (int i = 0; i < rows_per_warp; i++) {
        const int row = (blockIdx.x * 8 + w) * rows_per_warp + i;
        const unsigned idx = 0xFFFFFFFFu - (unsigned)(g_best[row] & 0xFFFFFFFFull);
        const float4* a = (const float4*)(g_xn + (size_t)row * D) + lane * 2;
        const float4* b = (const float4*)(g_xn + (size_t)idx * D) + lane * 2;
        float4 a0 = a[0], a1 = a[1], b0 = b[0], b1 = b[1];
        float d, s = 0.f;
        d = a0.x-b0.x+EPSF; s += d*d;  d = a0.y-b0.y+EPSF; s += d*d;
        d = a0.z-b0.z+EPSF; s += d*d;  d = a0.w-b0.w+EPSF; s += d*d;
        d = a1.x-b1.x+EPSF; s += d*d;  d = a1.y-b1.y+EPSF; s += d*d;
        d = a1.z-b1.z+EPSF; s += d*d;  d = a1.w-b1.w+EPSF; s += d*d;
        #pragma unroll
        for (int o = 16; o; o >>= 1) s += __shfl_xor_sync(0xffffffffu, s, o);
        if (lane == 0) wsum += -logf(sqrtf(s) + EPSF);
    }
    __shared__ float sm[8];
    if (lane == 0) sm[w] = wsum;
    __syncthreads();
    if (threadIdx.x == 0) {
        float b = 0.f;
        #pragma unroll
        for (int i = 0; i < 8; i++) b += sm[i];
        g_part[blockIdx.x] = b;
        __threadfence();
        if (atomicAdd(&g_ctr, 1) == RB - 1) {
            float tot = 0.f;
            for (int i = 0; i < RB; i++) tot += g_part[i];   // fixed order
            out[0] = tot / (float)n;
        }
    }
}

// ---------------------------------------------------------------- launch
extern "C" void kernel_launch(void* const* d_in, const int* in_sizes, int n_in,
                              void* d_out, int out_size) {
    const float* student = (const float*)d_in[0];
    int n = in_sizes[0] / D / 10;          // B = 8192
    if (n > NMAX) n = NMAX;
    const int nb = n / TB;
    const int ntiles = nb * (nb + 1) / 2;

    static bool attr_set = false;
    if (!attr_set) {
        cudaFuncSetAttribute(k_dots_mma,
                             cudaFuncAttributeMaxDynamicSharedMemorySize, SMEMB);
        attr_set = true;
    }

    k_normalize<<<(n + 7) / 8, 256>>>(student, n);
    k_dots_mma<<<ntiles, 128, SMEMB>>>(nb);
    k_dist_reduce<<<RB, 256>>>((float*)d_out, n);
}